// round 2
// baseline (speedup 1.0000x reference)
#include <cuda_runtime.h>
#include <math.h>

#define NN 100000
#define EE 400000
#define GG 4096
#define EMB 128
#define LN2F 0.6931471805599453f

__device__ float    g_ha  [NN * EMB];
__device__ float    g_hb  [NN * EMB];
__device__ float    g_PQ  [NN * 2 * EMB];   // [P | Q] per node, pitch 256
__device__ float    g_S   [NN * EMB];
__device__ float    g_Rm  [NN * EMB];
__device__ float    g_acc [NN * EMB];
__device__ unsigned g_agg [NN * EMB];
__device__ int      g_deg [NN];
__device__ float    g_pool[GG * EMB];
__device__ float    g_comb[EMB * 2 * EMB];  // [W1-W2 | W2]
__device__ float    g_cvec[EMB];

__device__ __forceinline__ float sp(float x) {
    return fmaxf(x, 0.f) + log1pf(expf(-fabsf(x)));
}
__device__ __forceinline__ unsigned fkey(float f) {
    unsigned u = __float_as_uint(f);
    return (u & 0x80000000u) ? ~u : (u | 0x80000000u);
}
__device__ __forceinline__ float finv(unsigned u) {
    return (u & 0x80000000u) ? __uint_as_float(u & 0x7FFFFFFFu) : __uint_as_float(~u);
}
__device__ __forceinline__ float tf32_rna(float x) {
    unsigned r; asm("cvt.rna.tf32.f32 %0, %1;" : "=r"(r) : "f"(x));
    return __uint_as_float(r);
}
__device__ __forceinline__ void mma_tf32(float* d, const unsigned* a, const unsigned* b) {
    asm volatile(
        "mma.sync.aligned.m16n8k8.row.col.f32.tf32.tf32.f32 "
        "{%0,%1,%2,%3}, {%4,%5,%6,%7}, {%8,%9}, {%0,%1,%2,%3};\n"
        : "+f"(d[0]), "+f"(d[1]), "+f"(d[2]), "+f"(d[3])
        : "r"(a[0]), "r"(a[1]), "r"(a[2]), "r"(a[3]), "r"(b[0]), "r"(b[1]));
}

// ---------------- setup kernels ----------------
__global__ void embed_sp_kernel(const float* __restrict__ emb, const int* __restrict__ ids,
                                float* __restrict__ out, int rows) {
    int t = blockIdx.x * blockDim.x + threadIdx.x;
    if (t >= rows * 32) return;
    int n = t >> 5, l = t & 31;
    const float4* e4 = (const float4*)emb;
    float4 v = e4[ids[n] * 32 + l];
    float4 o = make_float4(sp(v.x), sp(v.y), sp(v.z), sp(v.w));
    ((float4*)out)[(size_t)n * 32 + l] = o;
}

__global__ void count_deg_kernel(const int* __restrict__ dst) {
    int e = blockIdx.x * blockDim.x + threadIdx.x;
    if (e < EE) atomicAdd(&g_deg[dst[e]], 1);
}

__global__ void build_comb_kernel(const float* __restrict__ Wb) {
    int idx = blockIdx.x * blockDim.x + threadIdx.x;
    if (idx >= EMB * 2 * EMB) return;
    int k = idx >> 8, j = idx & 255;
    float v;
    if (j < EMB) v = Wb[k * EMB + j] - Wb[(k + EMB) * EMB + j];
    else         v = Wb[(k + EMB) * EMB + (j - EMB)];
    g_comb[k * 256 + j] = v;
}

__global__ void build_cvec_kernel(const float* __restrict__ We) {
    int j = threadIdx.x;
    float s = 0.f;
    for (int k = 0; k < EMB; k++) s += We[k * EMB + j];
    g_cvec[j] = LN2F * s;
}

// ---------------- tf32 tensor-core GEMM (3xTF32): C[M x Nc] = A[M x 128] @ W[128 x Nc] ----
// Block tile 128x128, 256 threads = 8 warps (4m x 2n), warp tile 32x64.
// K processed in 8 chunks of 16. smem holds (hi,lo) float2 pairs.
__global__ __launch_bounds__(256, 2)
void gemm_tf32_3x(const float* __restrict__ A, const float* __restrict__ W,
                  float* __restrict__ C, int M, int Nc) {
    __shared__ float2 sA[128][20];   // [m][k]  pitch2=20  (mod16=4 -> frag LDS at floor)
    __shared__ float2 sB[16][136];   // [k][n]  pitch2=136 (mod16=8 -> frag LDS at floor)

    const int tid  = threadIdx.x;
    const int lane = tid & 31;
    const int warp = tid >> 5;
    const int g    = lane >> 2;
    const int c    = lane & 3;
    const int wm   = warp >> 1;      // 0..3
    const int wn   = warp & 1;       // 0..1
    const int bm   = blockIdx.x * 128;
    const int bn   = blockIdx.y * 128;

    float acc[2][8][4];
#pragma unroll
    for (int mf = 0; mf < 2; mf++)
#pragma unroll
        for (int nf = 0; nf < 8; nf++)
#pragma unroll
            for (int i = 0; i < 4; i++) acc[mf][nf][i] = 0.f;

    float4 abuf[2];
    float  bbuf[8];

    // prologue: load chunk 0
    {
        const int kb = 0;
#pragma unroll
        for (int i = 0; i < 2; i++) {
            int idx = tid + i * 256, row = idx >> 2, c4 = idx & 3;
            int gr = bm + row;
            abuf[i] = (gr < M) ? *(const float4*)&A[(size_t)gr * 128 + kb + c4 * 4]
                               : make_float4(0.f, 0.f, 0.f, 0.f);
        }
#pragma unroll
        for (int i = 0; i < 8; i++) {
            int idx = tid + i * 256, kB = idx >> 7, n = idx & 127;
            bbuf[i] = W[(size_t)(kb + kB) * Nc + bn + n];
        }
    }

    for (int chunk = 0; chunk < 8; chunk++) {
        // store hi/lo split to smem
#pragma unroll
        for (int i = 0; i < 2; i++) {
            int idx = tid + i * 256, row = idx >> 2, c4 = idx & 3;
            const float* v = (const float*)&abuf[i];
#pragma unroll
            for (int j = 0; j < 4; j++) {
                float hi = tf32_rna(v[j]);
                float lo = tf32_rna(v[j] - hi);
                sA[row][c4 * 4 + j] = make_float2(hi, lo);
            }
        }
#pragma unroll
        for (int i = 0; i < 8; i++) {
            int idx = tid + i * 256, kB = idx >> 7, n = idx & 127;
            float hi = tf32_rna(bbuf[i]);
            float lo = tf32_rna(bbuf[i] - hi);
            sB[kB][n] = make_float2(hi, lo);
        }
        __syncthreads();

        // prefetch next chunk into registers (latency hidden by compute)
        if (chunk < 7) {
            const int kb = (chunk + 1) * 16;
#pragma unroll
            for (int i = 0; i < 2; i++) {
                int idx = tid + i * 256, row = idx >> 2, c4 = idx & 3;
                int gr = bm + row;
                abuf[i] = (gr < M) ? *(const float4*)&A[(size_t)gr * 128 + kb + c4 * 4]
                                   : make_float4(0.f, 0.f, 0.f, 0.f);
            }
#pragma unroll
            for (int i = 0; i < 8; i++) {
                int idx = tid + i * 256, kB = idx >> 7, n = idx & 127;
                bbuf[i] = W[(size_t)(kb + kB) * Nc + bn + n];
            }
        }

        // compute: 2 k8 steps
#pragma unroll
        for (int ks = 0; ks < 16; ks += 8) {
            unsigned ah[2][4], al[2][4];
#pragma unroll
            for (int mf = 0; mf < 2; mf++) {
                int r0 = wm * 32 + mf * 16 + g;
                float2 a0 = sA[r0][ks + c];
                float2 a1 = sA[r0 + 8][ks + c];
                float2 a2 = sA[r0][ks + c + 4];
                float2 a3 = sA[r0 + 8][ks + c + 4];
                ah[mf][0] = __float_as_uint(a0.x); al[mf][0] = __float_as_uint(a0.y);
                ah[mf][1] = __float_as_uint(a1.x); al[mf][1] = __float_as_uint(a1.y);
                ah[mf][2] = __float_as_uint(a2.x); al[mf][2] = __float_as_uint(a2.y);
                ah[mf][3] = __float_as_uint(a3.x); al[mf][3] = __float_as_uint(a3.y);
            }
#pragma unroll
            for (int nf = 0; nf < 8; nf++) {
                int nn = wn * 64 + nf * 8 + g;
                float2 b0 = sB[ks + c][nn];
                float2 b1 = sB[ks + c + 4][nn];
                unsigned bh[2] = {__float_as_uint(b0.x), __float_as_uint(b1.x)};
                unsigned bl[2] = {__float_as_uint(b0.y), __float_as_uint(b1.y)};
#pragma unroll
                for (int mf = 0; mf < 2; mf++) {
                    mma_tf32(acc[mf][nf], ah[mf], bh);
                    mma_tf32(acc[mf][nf], al[mf], bh);
                    mma_tf32(acc[mf][nf], ah[mf], bl);
                }
            }
        }
        __syncthreads();
    }

    // epilogue
#pragma unroll
    for (int mf = 0; mf < 2; mf++) {
        int row = bm + wm * 32 + mf * 16 + g;
#pragma unroll
        for (int nf = 0; nf < 8; nf++) {
            int col = bn + wn * 64 + nf * 8 + c * 2;
            if (row < M)
                *(float2*)&C[(size_t)row * Nc + col] = make_float2(acc[mf][nf][0], acc[mf][nf][1]);
            if (row + 8 < M)
                *(float2*)&C[(size_t)(row + 8) * Nc + col] = make_float2(acc[mf][nf][2], acc[mf][nf][3]);
        }
    }
}

// ---------------- edge phase 1: scatter-max of Q[src] (P factored out of max) -----
__global__ void edge_max_kernel(const int* __restrict__ src, const int* __restrict__ dst) {
    int e = blockIdx.x * 8 + (threadIdx.x >> 5);
    if (e >= EE) return;
    int l = threadIdx.x & 31;
    int d = dst[e], s = src[e];
    float4 q = ((const float4*)g_PQ)[(size_t)s * 64 + 32 + l];
    unsigned* a = &g_agg[(size_t)d * 128 + l * 4];
    atomicMax(a + 0, fkey(q.x));
    atomicMax(a + 1, fkey(q.y));
    atomicMax(a + 2, fkey(q.z));
    atomicMax(a + 3, fkey(q.w));
}

__global__ void update_hb_kernel(const float* __restrict__ b_bond) {
    int idx = blockIdx.x * blockDim.x + threadIdx.x;
    if (idx >= NN * EMB) return;
    int n = idx >> 7, k = idx & 127;
    float v = (g_deg[n] > 0) ? sp(finv(g_agg[idx]) + g_PQ[(size_t)n * 256 + k] + b_bond[k])
                             : LN2F;
    g_hb[idx] = v;
}

// ---------------- edge phase 2: scatter-add of Rm[src]+S[e] ----------------
__global__ void edge_add_kernel(const int* __restrict__ src, const int* __restrict__ dst) {
    int e = blockIdx.x * 8 + (threadIdx.x >> 5);
    if (e >= EE) return;
    int l = threadIdx.x & 31;
    int d = dst[e], s = src[e];
    float4 r = ((const float4*)g_Rm)[(size_t)s * 32 + l];
    float4 sv = (e < NN) ? ((const float4*)g_S)[(size_t)e * 32 + l]
                         : ((const float4*)g_cvec)[l];
    float* a = &g_acc[(size_t)d * 128 + l * 4];
    atomicAdd(a + 0, r.x + sv.x);
    atomicAdd(a + 1, r.y + sv.y);
    atomicAdd(a + 2, r.z + sv.z);
    atomicAdd(a + 3, r.w + sv.w);
}

__global__ void update_ha_kernel(const float* __restrict__ b_msg, const float* __restrict__ b_edge) {
    int idx = blockIdx.x * blockDim.x + threadIdx.x;
    if (idx >= NN * EMB) return;
    int n = idx >> 7, k = idx & 127;
    float b = b_msg[k] + b_edge[k];
    g_ha[idx] = sp(g_acc[idx] + (float)g_deg[n] * b + g_ha[idx]);
}

// ---------------- pooling + readout ----------------
__global__ void pool_kernel(const int* __restrict__ batch) {
    int t = blockIdx.x * blockDim.x + threadIdx.x;
    if (t >= NN * 32) return;
    int n = t >> 5, l = t & 31;
    int g = batch[n];
    float4 v = ((const float4*)g_ha)[(size_t)n * 32 + l];
    float* p = &g_pool[(size_t)g * 128 + l * 4];
    atomicAdd(p + 0, v.x);
    atomicAdd(p + 1, v.y);
    atomicAdd(p + 2, v.z);
    atomicAdd(p + 3, v.w);
}

__global__ void readout_kernel(const float* __restrict__ Wr1, const float* __restrict__ br1,
                               const float* __restrict__ Wr2, const float* __restrict__ br2,
                               const float* __restrict__ Wr3, const float* __restrict__ br3,
                               float* __restrict__ out) {
    __shared__ float pv[128];
    __shared__ float h1[64];
    __shared__ float h2[64];
    __shared__ float red[2];
    int g = blockIdx.x;
    int t = threadIdx.x;
    pv[t]      = g_pool[(size_t)g * 128 + t];
    pv[t + 64] = g_pool[(size_t)g * 128 + 64 + t];
    __syncthreads();
    float a1 = br1[t];
#pragma unroll 8
    for (int k = 0; k < 128; k++) a1 += pv[k] * Wr1[k * 64 + t];
    h1[t] = sp(a1);
    __syncthreads();
    float a2 = br2[t];
#pragma unroll 8
    for (int k = 0; k < 64; k++) a2 += h1[k] * Wr2[k * 64 + t];
    h2[t] = sp(a2);
    __syncthreads();
    float v = h2[t] * Wr3[t];
#pragma unroll
    for (int o = 16; o > 0; o >>= 1) v += __shfl_down_sync(0xffffffffu, v, o);
    if ((t & 31) == 0) red[t >> 5] = v;
    __syncthreads();
    if (t == 0) out[g] = red[0] + red[1] + br3[0];
}

// ---------------- output writers ----------------
__global__ void write_ha_kernel(float* __restrict__ out) {
    int t = blockIdx.x * blockDim.x + threadIdx.x;
    if (t >= NN * 32) return;
    ((float4*)out)[t] = ((const float4*)g_ha)[t];
}
__global__ void write_hb_kernel(float* __restrict__ out) {
    int t = blockIdx.x * blockDim.x + threadIdx.x;
    if (t >= EE * 32) return;
    int e = t >> 5;
    float4 v;
    if (e < NN) v = ((const float4*)g_hb)[t];
    else        v = make_float4(LN2F, LN2F, LN2F, LN2F);
    ((float4*)out)[t] = v;
}

// ---------------- launch ----------------
extern "C" void kernel_launch(void* const* d_in, const int* in_sizes, int n_in,
                              void* d_out, int out_size) {
    const int*   x_ids      = (const int*)d_in[0];
    const int*   edge_attr  = (const int*)d_in[1];
    const int*   edge_index = (const int*)d_in[2];
    const int*   batch      = (const int*)d_in[3];
    const float* emb_atom   = (const float*)d_in[4];
    const float* emb_bond   = (const float*)d_in[5];
    const float* W_bond     = (const float*)d_in[6];
    const float* b_bond     = (const float*)d_in[7];
    const float* W_msg      = (const float*)d_in[8];
    const float* b_msg      = (const float*)d_in[9];
    const float* W_edge     = (const float*)d_in[10];
    const float* b_edge     = (const float*)d_in[11];
    const float* W_r1       = (const float*)d_in[12];
    const float* b_r1       = (const float*)d_in[13];
    const float* W_r2       = (const float*)d_in[14];
    const float* b_r2       = (const float*)d_in[15];
    const float* W_r3       = (const float*)d_in[16];
    const float* b_r3       = (const float*)d_in[17];

    const int* src = edge_index;
    const int* dst = edge_index + EE;

    float* out_g  = (float*)d_out;
    float* out_ha = out_g + GG;
    float* out_hb = out_ha + (size_t)NN * EMB;

    void *p_agg, *p_acc, *p_deg, *p_pool, *p_ha, *p_hb, *p_PQ, *p_S, *p_Rm, *p_comb;
    cudaGetSymbolAddress(&p_agg,  g_agg);
    cudaGetSymbolAddress(&p_acc,  g_acc);
    cudaGetSymbolAddress(&p_deg,  g_deg);
    cudaGetSymbolAddress(&p_pool, g_pool);
    cudaGetSymbolAddress(&p_ha,   g_ha);
    cudaGetSymbolAddress(&p_hb,   g_hb);
    cudaGetSymbolAddress(&p_PQ,   g_PQ);
    cudaGetSymbolAddress(&p_S,    g_S);
    cudaGetSymbolAddress(&p_Rm,   g_Rm);
    cudaGetSymbolAddress(&p_comb, g_comb);

    const int T = 256;
    int blk_n32  = (NN * 32 + T - 1) / T;
    int blk_n128 = (NN * EMB + T - 1) / T;
    int blk_e    = EE / 8;
    int blk_e32  = (EE * 32 + T - 1) / T;
    int gm128    = (NN + 127) / 128;   // 782

    cudaMemsetAsync(p_deg, 0, NN * sizeof(int));
    embed_sp_kernel<<<blk_n32, T>>>(emb_atom, x_ids, (float*)p_ha, NN);
    embed_sp_kernel<<<blk_n32, T>>>(emb_bond, edge_attr, (float*)p_hb, NN);
    count_deg_kernel<<<(EE + T - 1) / T, T>>>(dst);
    build_comb_kernel<<<(EMB * 2 * EMB + T - 1) / T, T>>>(W_bond);
    build_cvec_kernel<<<1, 128>>>(W_edge);

    for (int pass = 0; pass < 2; pass++) {
        dim3 gpq(gm128, 2);
        gemm_tf32_3x<<<gpq, T>>>((const float*)p_hb, (const float*)p_comb, (float*)p_PQ, NN, 256);
        cudaMemsetAsync(p_agg, 0, (size_t)NN * EMB * sizeof(unsigned));
        edge_max_kernel<<<blk_e, T>>>(src, dst);
        update_hb_kernel<<<blk_n128, T>>>(b_bond);
        dim3 g1(gm128, 1);
        gemm_tf32_3x<<<g1, T>>>((const float*)p_hb, W_edge, (float*)p_S, NN, 128);
        gemm_tf32_3x<<<g1, T>>>((const float*)p_ha, W_msg, (float*)p_Rm, NN, 128);
        cudaMemsetAsync(p_acc, 0, (size_t)NN * EMB * sizeof(float));
        edge_add_kernel<<<blk_e, T>>>(src, dst);
        update_ha_kernel<<<blk_n128, T>>>(b_msg, b_edge);
    }

    cudaMemsetAsync(p_pool, 0, (size_t)GG * EMB * sizeof(float));
    pool_kernel<<<blk_n32, T>>>(batch);
    readout_kernel<<<GG, 64>>>(W_r1, b_r1, W_r2, b_r2, W_r3, b_r3, out_g);

    write_ha_kernel<<<blk_n32, T>>>(out_ha);
    write_hb_kernel<<<blk_e32, T>>>(out_hb);
}

// round 3
// speedup vs baseline: 1.2963x; 1.2963x over previous
#include <cuda_runtime.h>
#include <math.h>
#include <float.h>

#define NN 100000
#define EE 400000
#define GG 4096
#define EMB 128
#define LN2F 0.6931471805599453f

// ---------------- scratch ----------------
__device__ float g_ha  [NN * EMB];
__device__ float g_hb  [NN * EMB];
__device__ float g_PQ  [NN * 2 * EMB];   // [P | Q], pitch 256
__device__ float g_X   [NN * 2 * EMB];   // [U | T], pitch 256
__device__ float g_comb[EMB * 2 * EMB];  // [W1-W2 | W2]  (128 x 256)
__device__ float g_wcat[2 * EMB * EMB];  // [W_msg ; W_edge] (256 x 128)
__device__ int   g_deg [NN];
__device__ int   g_off [NN + 1];
__device__ int   g_fill[NN];
__device__ int   g_bsumA[128];
__device__ int   g_boff [128];
__device__ int   g_csr_src[EE];
__device__ int   g_csr_eid[EE];
__device__ int   g_gstart[GG + 1];

__device__ __forceinline__ float sp(float x) {
    return fmaxf(x, 0.f) + log1pf(expf(-fabsf(x)));
}
__device__ __forceinline__ float4 max4(float4 a, float4 b) {
    return make_float4(fmaxf(a.x,b.x), fmaxf(a.y,b.y), fmaxf(a.z,b.z), fmaxf(a.w,b.w));
}

// ---------------- setup ----------------
__global__ void embed_sp_kernel(const float* __restrict__ emb, const int* __restrict__ ids,
                                float* __restrict__ out, int rows) {
    int t = blockIdx.x * blockDim.x + threadIdx.x;
    if (t >= rows * 32) return;
    int n = t >> 5, l = t & 31;
    float4 v = ((const float4*)emb)[ids[n] * 32 + l];
    ((float4*)out)[(size_t)n * 32 + l] = make_float4(sp(v.x), sp(v.y), sp(v.z), sp(v.w));
}

__global__ void count_deg_kernel(const int* __restrict__ dst) {
    int e = blockIdx.x * blockDim.x + threadIdx.x;
    if (e < EE) atomicAdd(&g_deg[dst[e]], 1);
}

__global__ void scan1_kernel() {
    __shared__ int s[1024];
    int t = threadIdx.x;
    int n = blockIdx.x * 1024 + t;
    int v = (n < NN) ? g_deg[n] : 0;
    s[t] = v;
    __syncthreads();
    for (int off = 1; off < 1024; off <<= 1) {
        int add = (t >= off) ? s[t - off] : 0;
        __syncthreads();
        s[t] += add;
        __syncthreads();
    }
    if (n < NN) g_off[n] = s[t] - v;   // exclusive within block
    if (t == 1023) g_bsumA[blockIdx.x] = s[1023];
}

__global__ void scan2_kernel(int nblk) {
    if (threadIdx.x == 0) {
        int run = 0;
        for (int i = 0; i < nblk; i++) { int v = g_bsumA[i]; g_boff[i] = run; run += v; }
    }
}

__global__ void scan3_kernel() {
    int n = blockIdx.x * blockDim.x + threadIdx.x;
    if (n < NN) g_off[n] += g_boff[n >> 10];
    if (n == 0) g_off[NN] = EE;
}

__global__ void fill_csr_kernel(const int* __restrict__ src, const int* __restrict__ dst) {
    int e = blockIdx.x * blockDim.x + threadIdx.x;
    if (e >= EE) return;
    int d = dst[e];
    int pos = atomicAdd(&g_fill[d], 1);
    int idx = g_off[d] + pos;
    g_csr_src[idx] = src[e];
    g_csr_eid[idx] = e;
}

__global__ void bounds_kernel(const int* __restrict__ batch) {
    int n = blockIdx.x * blockDim.x + threadIdx.x;
    if (n >= NN) return;
    int b = batch[n];
    int prev = (n == 0) ? -1 : batch[n - 1];
    for (int g = prev + 1; g <= b; g++) g_gstart[g] = n;
    if (n == NN - 1)
        for (int g = b + 1; g <= GG; g++) g_gstart[g] = NN;
}

__global__ void build_comb_kernel(const float* __restrict__ Wb) {
    int idx = blockIdx.x * blockDim.x + threadIdx.x;
    if (idx >= EMB * 2 * EMB) return;
    int k = idx >> 8, j = idx & 255;
    float v;
    if (j < EMB) v = Wb[k * EMB + j] - Wb[(k + EMB) * EMB + j];
    else         v = Wb[(k + EMB) * EMB + (j - EMB)];
    g_comb[k * 256 + j] = v;
}

__global__ void build_wcat_kernel(const float* __restrict__ Wm, const float* __restrict__ We) {
    int idx = blockIdx.x * blockDim.x + threadIdx.x;
    if (idx >= 2 * EMB * EMB) return;
    int r = idx >> 7, c = idx & 127;
    g_wcat[idx] = (r < EMB) ? Wm[r * EMB + c] : We[(r - EMB) * EMB + c];
}

// ---------------- SIMT fp32 GEMM: C[M x Nc] = A[M x K] @ W[K x Nc] ----------------
// 128x128 block tile, 256 threads, 8x8 microtile. Optional fused epilogue:
// if bmsg != null:  C = sp(acc + deg[row]*(bmsg[col]+bedge[col]) + C_old), also -> out2.
__global__ __launch_bounds__(256)
void gemm_simt(const float* __restrict__ A, const float* __restrict__ W,
               float* __restrict__ C, int M, int K, int Nc,
               const float* __restrict__ bmsg, const float* __restrict__ bedge,
               const int* __restrict__ degp, float* __restrict__ out2) {
    __shared__ float sA[16][132];   // [k][m] transposed
    __shared__ float sB[16][132];   // [k][n]

    const int tid  = threadIdx.x;
    const int lane = tid & 31;
    const int warp = tid >> 5;
    const int tr   = lane >> 3, tc = lane & 7;
    const int wm   = warp >> 1, wn = warp & 1;
    const int bm   = blockIdx.x * 128;
    const int bn   = blockIdx.y * 128;
    const int mrow = wm * 32 + tr * 8;
    const int ncol = wn * 64 + tc * 8;

    float acc[8][8];
#pragma unroll
    for (int i = 0; i < 8; i++)
#pragma unroll
        for (int j = 0; j < 8; j++) acc[i][j] = 0.f;

    const int a_row0 = tid >> 2;      // + i*64
    const int a_c4   = tid & 3;
    const int b_k0   = tid >> 5;      // + i*8
    const int b_n4   = tid & 31;

    float4 abuf[2], bbuf[2];
    const int chunks = K >> 4;

    // prologue
#pragma unroll
    for (int i = 0; i < 2; i++) {
        int gr = bm + a_row0 + i * 64;
        abuf[i] = (gr < M) ? *(const float4*)&A[(size_t)gr * K + a_c4 * 4]
                           : make_float4(0.f, 0.f, 0.f, 0.f);
        bbuf[i] = *(const float4*)&W[(size_t)(b_k0 + i * 8) * Nc + bn + b_n4 * 4];
    }

    for (int ch = 0; ch < chunks; ch++) {
#pragma unroll
        for (int i = 0; i < 2; i++) {
            int row = a_row0 + i * 64;
            const float* v = (const float*)&abuf[i];
#pragma unroll
            for (int j = 0; j < 4; j++) sA[a_c4 * 4 + j][row] = v[j];
            *(float4*)&sB[b_k0 + i * 8][b_n4 * 4] = bbuf[i];
        }
        __syncthreads();

        if (ch < chunks - 1) {
            int kb = (ch + 1) * 16;
#pragma unroll
            for (int i = 0; i < 2; i++) {
                int gr = bm + a_row0 + i * 64;
                abuf[i] = (gr < M) ? *(const float4*)&A[(size_t)gr * K + kb + a_c4 * 4]
                                   : make_float4(0.f, 0.f, 0.f, 0.f);
                bbuf[i] = *(const float4*)&W[(size_t)(kb + b_k0 + i * 8) * Nc + bn + b_n4 * 4];
            }
        }

#pragma unroll
        for (int k = 0; k < 16; k++) {
            float a[8], b[8];
            *(float4*)&a[0] = *(const float4*)&sA[k][mrow];
            *(float4*)&a[4] = *(const float4*)&sA[k][mrow + 4];
            *(float4*)&b[0] = *(const float4*)&sB[k][ncol];
            *(float4*)&b[4] = *(const float4*)&sB[k][ncol + 4];
#pragma unroll
            for (int i = 0; i < 8; i++)
#pragma unroll
                for (int j = 0; j < 8; j++) acc[i][j] += a[i] * b[j];
        }
        __syncthreads();
    }

    // epilogue
    if (!bmsg) {
#pragma unroll
        for (int i = 0; i < 8; i++) {
            int gr = bm + mrow + i;
            if (gr < M) {
                *(float4*)&C[(size_t)gr * Nc + bn + ncol]     = *(float4*)&acc[i][0];
                *(float4*)&C[(size_t)gr * Nc + bn + ncol + 4] = *(float4*)&acc[i][4];
            }
        }
    } else {
        float bs[8];
#pragma unroll
        for (int j = 0; j < 8; j++) {
            int gc = bn + ncol + j;
            bs[j] = bmsg[gc] + bedge[gc];
        }
#pragma unroll
        for (int i = 0; i < 8; i++) {
            int gr = bm + mrow + i;
            if (gr < M) {
                float dg = (float)degp[gr];
                float4 o0 = *(const float4*)&C[(size_t)gr * Nc + bn + ncol];
                float4 o1 = *(const float4*)&C[(size_t)gr * Nc + bn + ncol + 4];
                float4 v0 = make_float4(sp(acc[i][0] + dg * bs[0] + o0.x),
                                        sp(acc[i][1] + dg * bs[1] + o0.y),
                                        sp(acc[i][2] + dg * bs[2] + o0.z),
                                        sp(acc[i][3] + dg * bs[3] + o0.w));
                float4 v1 = make_float4(sp(acc[i][4] + dg * bs[4] + o1.x),
                                        sp(acc[i][5] + dg * bs[5] + o1.y),
                                        sp(acc[i][6] + dg * bs[6] + o1.z),
                                        sp(acc[i][7] + dg * bs[7] + o1.w));
                *(float4*)&C[(size_t)gr * Nc + bn + ncol]     = v0;
                *(float4*)&C[(size_t)gr * Nc + bn + ncol + 4] = v1;
                if (out2) {
                    *(float4*)&out2[(size_t)gr * Nc + bn + ncol]     = v0;
                    *(float4*)&out2[(size_t)gr * Nc + bn + ncol + 4] = v1;
                }
            }
        }
    }
}

// ---------------- CSR aggregations (warp per node, no atomics) ----------------
__global__ void agg_max_kernel(const float* __restrict__ b_bond, float* __restrict__ out2) {
    int nid = blockIdx.x * 8 + (threadIdx.x >> 5);
    if (nid >= NN) return;
    int l = threadIdx.x & 31;
    int o0 = g_off[nid], o1 = g_off[nid + 1];
    const float4* PQ4 = (const float4*)g_PQ;
    float4 res;
    if (o1 > o0) {
        float4 m = make_float4(-FLT_MAX, -FLT_MAX, -FLT_MAX, -FLT_MAX);
        for (int i = o0; i < o1; i++) {
            int s = g_csr_src[i];
            m = max4(m, PQ4[(size_t)s * 64 + 32 + l]);
        }
        float4 p  = PQ4[(size_t)nid * 64 + l];
        float4 bb = ((const float4*)b_bond)[l];
        res = make_float4(sp(m.x + p.x + bb.x), sp(m.y + p.y + bb.y),
                          sp(m.z + p.z + bb.z), sp(m.w + p.w + bb.w));
    } else {
        res = make_float4(LN2F, LN2F, LN2F, LN2F);
    }
    ((float4*)g_hb)[(size_t)nid * 32 + l] = res;
    if (out2) ((float4*)out2)[(size_t)nid * 32 + l] = res;
}

__global__ void agg_sum_kernel() {
    int nid = blockIdx.x * 8 + (threadIdx.x >> 5);
    if (nid >= NN) return;
    int l = threadIdx.x & 31;
    int o0 = g_off[nid], o1 = g_off[nid + 1];
    const float4* ha4 = (const float4*)g_ha;
    const float4* hb4 = (const float4*)g_hb;
    float4 u = make_float4(0.f, 0.f, 0.f, 0.f);
    float4 t = make_float4(0.f, 0.f, 0.f, 0.f);
    float cge = 0.f;
    for (int i = o0; i < o1; i++) {
        int s = g_csr_src[i];
        int e = g_csr_eid[i];
        float4 av = ha4[(size_t)s * 32 + l];
        u.x += av.x; u.y += av.y; u.z += av.z; u.w += av.w;
        if (e < NN) {
            float4 bv = hb4[(size_t)e * 32 + l];
            t.x += bv.x; t.y += bv.y; t.z += bv.z; t.w += bv.w;
        } else cge += 1.f;
    }
    float c = cge * LN2F;
    t.x += c; t.y += c; t.z += c; t.w += c;
    float4* X4 = (float4*)g_X;
    X4[(size_t)nid * 64 + l]      = u;
    X4[(size_t)nid * 64 + 32 + l] = t;
}

// ---------------- fused pool + readout (batch sorted -> contiguous ranges) ----------
__global__ void pool_readout_kernel(const float* __restrict__ Wr1, const float* __restrict__ br1,
                                    const float* __restrict__ Wr2, const float* __restrict__ br2,
                                    const float* __restrict__ Wr3, const float* __restrict__ br3,
                                    float* __restrict__ out) {
    __shared__ float pv[128];
    __shared__ float h1[64];
    __shared__ float h2[64];
    __shared__ float red[2];
    int g = blockIdx.x;
    int t = threadIdx.x;  // 128
    int s = g_gstart[g], e = g_gstart[g + 1];
    float sum = 0.f;
    for (int n = s; n < e; n++) sum += g_ha[(size_t)n * 128 + t];
    pv[t] = sum;
    __syncthreads();
    if (t < 64) {
        float a1 = br1[t];
#pragma unroll 8
        for (int k = 0; k < 128; k++) a1 += pv[k] * Wr1[k * 64 + t];
        h1[t] = sp(a1);
    }
    __syncthreads();
    if (t < 64) {
        float a2 = br2[t];
#pragma unroll 8
        for (int k = 0; k < 64; k++) a2 += h1[k] * Wr2[k * 64 + t];
        h2[t] = sp(a2);
    }
    __syncthreads();
    if (t < 64) {
        float v = h2[t] * Wr3[t];
#pragma unroll
        for (int o = 16; o > 0; o >>= 1) v += __shfl_down_sync(0xffffffffu, v, o);
        if ((t & 31) == 0) red[t >> 5] = v;
    }
    __syncthreads();
    if (t == 0) out[g] = red[0] + red[1] + br3[0];
}

// ---------------- constant tail of h_b output ----------------
__global__ void tail_hb_kernel(float* __restrict__ out_hb) {
    int t = blockIdx.x * blockDim.x + threadIdx.x;
    if (t >= (EE - NN) * 32) return;
    ((float4*)out_hb)[(size_t)NN * 32 + t] = make_float4(LN2F, LN2F, LN2F, LN2F);
}

// ---------------- launch ----------------
extern "C" void kernel_launch(void* const* d_in, const int* in_sizes, int n_in,
                              void* d_out, int out_size) {
    const int*   x_ids      = (const int*)d_in[0];
    const int*   edge_attr  = (const int*)d_in[1];
    const int*   edge_index = (const int*)d_in[2];
    const int*   batch      = (const int*)d_in[3];
    const float* emb_atom   = (const float*)d_in[4];
    const float* emb_bond   = (const float*)d_in[5];
    const float* W_bond     = (const float*)d_in[6];
    const float* b_bond     = (const float*)d_in[7];
    const float* W_msg      = (const float*)d_in[8];
    const float* b_msg      = (const float*)d_in[9];
    const float* W_edge     = (const float*)d_in[10];
    const float* b_edge     = (const float*)d_in[11];
    const float* W_r1       = (const float*)d_in[12];
    const float* b_r1       = (const float*)d_in[13];
    const float* W_r2       = (const float*)d_in[14];
    const float* b_r2       = (const float*)d_in[15];
    const float* W_r3       = (const float*)d_in[16];
    const float* b_r3       = (const float*)d_in[17];

    const int* src = edge_index;
    const int* dst = edge_index + EE;

    float* out_g  = (float*)d_out;
    float* out_ha = out_g + GG;
    float* out_hb = out_ha + (size_t)NN * EMB;

    void *p_deg, *p_fill, *p_ha, *p_hb, *p_PQ, *p_X, *p_comb, *p_wcat;
    cudaGetSymbolAddress(&p_deg,  g_deg);
    cudaGetSymbolAddress(&p_fill, g_fill);
    cudaGetSymbolAddress(&p_ha,   g_ha);
    cudaGetSymbolAddress(&p_hb,   g_hb);
    cudaGetSymbolAddress(&p_PQ,   g_PQ);
    cudaGetSymbolAddress(&p_X,    g_X);
    cudaGetSymbolAddress(&p_comb, g_comb);
    cudaGetSymbolAddress(&p_wcat, g_wcat);

    const int T = 256;
    int blk_n32 = (NN * 32 + T - 1) / T;
    int blk_n   = (NN + T - 1) / T;
    int blk_e   = (EE + T - 1) / T;
    int blk_w   = (NN + 7) / 8;          // warp-per-node grids
    int gm128   = (NN + 127) / 128;      // 782
    int nblk_scan = (NN + 1023) / 1024;  // 98

    cudaMemsetAsync(p_deg,  0, NN * sizeof(int));
    cudaMemsetAsync(p_fill, 0, NN * sizeof(int));

    embed_sp_kernel<<<blk_n32, T>>>(emb_atom, x_ids, (float*)p_ha, NN);
    embed_sp_kernel<<<blk_n32, T>>>(emb_bond, edge_attr, (float*)p_hb, NN);
    count_deg_kernel<<<blk_e, T>>>(dst);
    scan1_kernel<<<nblk_scan, 1024>>>();
    scan2_kernel<<<1, 32>>>(nblk_scan);
    scan3_kernel<<<blk_n, T>>>();
    fill_csr_kernel<<<blk_e, T>>>(src, dst);
    bounds_kernel<<<blk_n, T>>>(batch);
    build_comb_kernel<<<(EMB * 2 * EMB + T - 1) / T, T>>>(W_bond);
    build_wcat_kernel<<<(2 * EMB * EMB + T - 1) / T, T>>>(W_msg, W_edge);

    for (int pass = 0; pass < 2; pass++) {
        bool last = (pass == 1);
        // EdgeConv: PQ = h_b @ [W1-W2 | W2]
        dim3 gr1(gm128, 2);
        gemm_simt<<<gr1, T>>>((const float*)p_hb, (const float*)p_comb, (float*)p_PQ,
                              NN, 128, 256, nullptr, nullptr, nullptr, nullptr);
        // h_b[d] = sp(max_e Q[src_e] + P[d] + b_bond)  (or ln2)
        agg_max_kernel<<<blk_w, T>>>(b_bond, last ? out_hb : nullptr);
        // X = [sum h_a[src] | sum h_b[eid]]
        agg_sum_kernel<<<blk_w, T>>>();
        // h_a = sp(X @ Wcat + deg*(b_msg+b_edge) + h_a)
        dim3 gr2(gm128, 1);
        gemm_simt<<<gr2, T>>>((const float*)p_X, (const float*)p_wcat, (float*)p_ha,
                              NN, 256, 128, b_msg, b_edge, (const int*)p_deg,
                              last ? out_ha : nullptr);
    }

    pool_readout_kernel<<<GG, 128>>>(W_r1, b_r1, W_r2, b_r2, W_r3, b_r3, out_g);
    tail_hb_kernel<<<((EE - NN) * 32 + T - 1) / T, T>>>(out_hb);
}